// round 10
// baseline (speedup 1.0000x reference)
#include <cuda_runtime.h>
#include <cstdint>

#define BATCH 16
#define NCLS 7
#define HH 368
#define WW 640
#define NSEG (BATCH * 6)

// Per-(b, class, row, warp) packed stats, padded to 8 words/row (32B) for
// aligned uint4 reads. Word: bits[0:10)=min col, [10:20)=max col,
// [20:31)=count (0 means empty for this class in this warp's 128 cols).
// Only warp-slots 0..4 are written; slots 5..7 stay zero (never written).
__device__ unsigned g_row5[NSEG * HH * 8];
__device__ float g_part[NSEG];

// -------------------------------------------------------------------------
// Kernel 1: per-pixel class via soft-argmax -> per-WARP per-class
// (min,max,count) stored directly; no smem, no barrier. 320-thread blocks
// cover TWO rows (warps 0-4 row A, warps 5-9 row B); 4 px per thread.
// Counts for all 6 classes are reduced with 2 packed REDUX.ADD instead of 6.
// -------------------------------------------------------------------------
__device__ __forceinline__ int pix_class(const float l[7]) {
    float e0 = __expf(l[0]);
    float e1 = __expf(l[1]);
    float e2 = __expf(l[2]);
    float e3 = __expf(l[3]);
    float e4 = __expf(l[4]);
    float e5 = __expf(l[5]);
    float e6 = __expf(l[6]);
    float den = ((e0 + e1) + (e2 + e3)) + ((e4 + e5) + e6);
    float num = e1;
    num = fmaf(2.0f, e2, num);
    num = fmaf(3.0f, e3, num);
    num = fmaf(4.0f, e4, num);
    num = fmaf(5.0f, e5, num);
    num = fmaf(6.0f, e6, num);
    // num/den in [0,6]; truncation == floor for non-negative values.
    float r = __fdividef(num, den);
    return (int)r;
}

__global__ __launch_bounds__(320, 6) void k_rowstats(const float* __restrict__ logits) {
    const int t    = threadIdx.x;
    const int lane = t & 31;
    const int half = (t >= 160);           // 0: warps 0-4, 1: warps 5-9
    const int tt   = t - half * 160;       // 0..159 within the row
    const int row  = blockIdx.x * 2 + half;
    const int b    = blockIdx.y;
    const int warp = tt >> 5;              // warp slot within the row (0..4)
    const int col0 = tt << 2;              // 4 pixels per thread

    float4 v[NCLS];
#pragma unroll
    for (int c = 0; c < NCLS; c++) {
        const float* p = logits + (((size_t)b * NCLS + c) * HH + row) * WW + col0;
        v[c] = *reinterpret_cast<const float4*>(p);
    }

    int k0, k1, k2, k3;
    {
        float l[7];
#pragma unroll
        for (int c = 0; c < NCLS; c++) l[c] = v[c].x;
        k0 = pix_class(l);
#pragma unroll
        for (int c = 0; c < NCLS; c++) l[c] = v[c].y;
        k1 = pix_class(l);
#pragma unroll
        for (int c = 0; c < NCLS; c++) l[c] = v[c].z;
        k2 = pix_class(l);
#pragma unroll
        for (int c = 0; c < NCLS; c++) l[c] = v[c].w;
        k3 = pix_class(l);
    }

    // One-hot bitboard: byte j holds (1 << class_of_pixel_j).
    const unsigned B = (1u << k0) | (1u << (k1 + 8)) | (1u << (k2 + 16)) | (1u << (k3 + 24));

    unsigned mymm = 0;          // lane c-1 keeps (mn | mx<<10) for class c
    unsigned pcA = 0, pcB = 0;  // packed per-lane counts: classes 1-3 / 4-6

#pragma unroll
    for (int c = 1; c <= 6; c++) {
        unsigned m = (B >> c) & 0x01010101u;  // bit 8*j set iff pixel j is class c
        int cnt = __popc(m);
        int mnl = m ? col0 + ((__ffs(m) - 1) >> 3) : 0x7fffffff;
        int mxl = m ? col0 + ((31 - __clz(m)) >> 3) : -1;
        int wmn = __reduce_min_sync(0xffffffffu, mnl);
        int wmx = __reduce_max_sync(0xffffffffu, mxl);
        if (c <= 3) pcA |= (unsigned)cnt << (10 * (c - 1));
        else        pcB |= (unsigned)cnt << (10 * (c - 4));
        if (lane == c - 1) {
            mymm = (unsigned)(wmn & 1023) | ((unsigned)(wmx & 1023) << 10);
        }
    }
    // Field-wise sums: each class count <= 128 per warp, fits 10-bit fields.
    pcA = __reduce_add_sync(0xffffffffu, pcA);
    pcB = __reduce_add_sync(0xffffffffu, pcB);

    if (lane < 6) {
        unsigned pcs = (lane < 3) ? pcA : pcB;
        unsigned fld = (lane < 3) ? lane : (lane - 3);
        unsigned cnt = (pcs >> (10 * fld)) & 1023;
        unsigned pk = cnt ? ((mymm & 0xFFFFFu) | (cnt << 20)) : 0u;
        g_row5[(((b * 6 + lane) * HH) + row) * 8 + warp] = pk;
    }
}

// -------------------------------------------------------------------------
// Kernel 2: one 32-thread block per segment (96 blocks). Lane owns 12
// contiguous rows; all 24 uint4 loads issued fully unrolled up-front
// (MLP=24), then fold 5 warp-slots per row, ordered in-lane merge, 5-step
// ordered warp tree. No smem, no barriers.
// -------------------------------------------------------------------------
__global__ __launch_bounds__(32) void k_combine() {
    const int seg  = blockIdx.x;
    const int lane = threadIdx.x;
    const int r0   = lane * 12;   // rows [r0, r0+12); 12*32=384 covers HH=368

    uint4 ua[12], ub[12];
#pragma unroll
    for (int i = 0; i < 12; i++) {
        const int r = r0 + i;
        if (r < HH) {
            const uint4* p = reinterpret_cast<const uint4*>(&g_row5[(seg * HH + r) * 8]);
            ua[i] = p[0];
            ub[i] = p[1];
        } else {
            ua[i] = make_uint4(0, 0, 0, 0);
            ub[i] = make_uint4(0, 0, 0, 0);
        }
    }

    int valid = 0, cnt = 0, S = 0;
    int fcol = 0, frow = 0, lcol = 0, lrow = 0;

#pragma unroll
    for (int i = 0; i < 12; i++) {
        const int r = r0 + i;
        unsigned pks[5] = {ua[i].x, ua[i].y, ua[i].z, ua[i].w, ub[i].x};
        int rc = 0, mnv = 0x7fffffff, mxv = -1;
#pragma unroll
        for (int s = 0; s < 5; s++) {
            unsigned pk = pks[s];
            int c = pk >> 20;
            if (c) {
                rc += c;
                mnv = min(mnv, (int)(pk & 1023));
                mxv = max(mxv, (int)((pk >> 10) & 1023));
            }
        }
        if (rc) {
            if (valid) {
                S += abs((mnv - r) - (lcol - lrow));
            } else {
                fcol = mnv; frow = r; valid = 1;
            }
            S += mxv - mnv;
            lcol = mxv; lrow = r; cnt += rc;
        }
    }

    // Ordered warp tree: lane absorbs the segment from lane+off (its right).
#pragma unroll
    for (int off = 1; off < 32; off <<= 1) {
        int ov  = __shfl_down_sync(0xffffffffu, valid, off);
        int oc  = __shfl_down_sync(0xffffffffu, cnt, off);
        int oS  = __shfl_down_sync(0xffffffffu, S, off);
        int ofc = __shfl_down_sync(0xffffffffu, fcol, off);
        int ofr = __shfl_down_sync(0xffffffffu, frow, off);
        int olc = __shfl_down_sync(0xffffffffu, lcol, off);
        int olr = __shfl_down_sync(0xffffffffu, lrow, off);
        if ((lane & (2 * off - 1)) == 0 && ov) {
            if (valid) {
                S += oS + abs((ofc - ofr) - (lcol - lrow));
            } else {
                S = oS; fcol = ofc; frow = ofr; valid = 1;
            }
            cnt += oc;
            lcol = olc; lrow = olr;
        }
    }

    if (lane == 0) {
        float loss = 0.0f;
        if (cnt >= 2) {
            loss = ((float)S / (float)(cnt - 1)) / (float)(cnt + 1);
        }
        g_part[seg] = loss;
    }
}

// -------------------------------------------------------------------------
// Kernel 3: deterministic sum of the 96 partials -> d_out[0].
// -------------------------------------------------------------------------
__global__ __launch_bounds__(128) void k_final(float* __restrict__ out) {
    const int t = threadIdx.x;
    float v = (t < NSEG) ? g_part[t] : 0.0f;
#pragma unroll
    for (int off = 16; off > 0; off >>= 1)
        v += __shfl_down_sync(0xffffffffu, v, off);
    __shared__ float sh[4];
    if ((t & 31) == 0) sh[t >> 5] = v;
    __syncthreads();
    if (t == 0) out[0] = (sh[0] + sh[1]) + (sh[2] + sh[3]);
}

extern "C" void kernel_launch(void* const* d_in, const int* in_sizes, int n_in,
                              void* d_out, int out_size) {
    const float* logits = (const float*)d_in[0];
    // d_in[1] (labels) is unused by the reference computation.
    dim3 g1(HH / 2, BATCH);
    k_rowstats<<<g1, 320>>>(logits);
    k_combine<<<NSEG, 32>>>();
    k_final<<<1, 128>>>((float*)d_out);
}

// round 11
// speedup vs baseline: 1.0115x; 1.0115x over previous
#include <cuda_runtime.h>
#include <cstdint>

#define BATCH 16
#define NCLS 7
#define HH 368
#define WW 640
#define NSEG (BATCH * 6)

// Per-(b, class, row, warp) packed stats, padded to 8 words/row (32B) for
// aligned uint4 reads. Word: bits[0:10)=min col, [10:20)=max col,
// [20:31)=count (0 means empty for this class in this warp's 128 cols).
// Only warp-slots 0..4 are written; slots 5..7 stay zero (never written).
__device__ unsigned g_row5[NSEG * HH * 8];
__device__ float g_part[NSEG];

// -------------------------------------------------------------------------
// Kernel 1: per-pixel class via soft-argmax -> per-WARP per-class
// (min,max,count) stored directly; no smem, no barrier. One 160-thread
// block covers TWO rows: every warp issues 14 independent float4 loads
// up-front (MLP=14), then computes row A stats, then row B stats.
// -------------------------------------------------------------------------
__device__ __forceinline__ int pix_class(const float l[7]) {
    float e0 = __expf(l[0]);
    float e1 = __expf(l[1]);
    float e2 = __expf(l[2]);
    float e3 = __expf(l[3]);
    float e4 = __expf(l[4]);
    float e5 = __expf(l[5]);
    float e6 = __expf(l[6]);
    float den = ((e0 + e1) + (e2 + e3)) + ((e4 + e5) + e6);
    float num = e1;
    num = fmaf(2.0f, e2, num);
    num = fmaf(3.0f, e3, num);
    num = fmaf(4.0f, e4, num);
    num = fmaf(5.0f, e5, num);
    num = fmaf(6.0f, e6, num);
    // num/den in [0,6]; truncation == floor for non-negative values.
    float r = __fdividef(num, den);
    return (int)r;
}

// Per-warp stats for one row-segment: returns packed word held by lanes 0-5
// (lane c-1 -> class c). col0 = first col of this thread's 4 pixels.
__device__ __forceinline__ unsigned seg_stats(const float4 v[NCLS], int col0, int lane) {
    int k0, k1, k2, k3;
    {
        float l[7];
#pragma unroll
        for (int c = 0; c < NCLS; c++) l[c] = v[c].x;
        k0 = pix_class(l);
#pragma unroll
        for (int c = 0; c < NCLS; c++) l[c] = v[c].y;
        k1 = pix_class(l);
#pragma unroll
        for (int c = 0; c < NCLS; c++) l[c] = v[c].z;
        k2 = pix_class(l);
#pragma unroll
        for (int c = 0; c < NCLS; c++) l[c] = v[c].w;
        k3 = pix_class(l);
    }

    // One-hot bitboard: byte j holds (1 << class_of_pixel_j).
    const unsigned B = (1u << k0) | (1u << (k1 + 8)) | (1u << (k2 + 16)) | (1u << (k3 + 24));

    unsigned mypk = 0;  // lane c-1 keeps class c's packed stats

#pragma unroll
    for (int c = 1; c <= 6; c++) {
        unsigned m = (B >> c) & 0x01010101u;  // bit 8*j set iff pixel j is class c
        int cnt = __popc(m);
        int mnl = m ? col0 + ((__ffs(m) - 1) >> 3) : 0x7fffffff;
        int mxl = m ? col0 + ((31 - __clz(m)) >> 3) : -1;
        int wmn = __reduce_min_sync(0xffffffffu, mnl);
        int wmx = __reduce_max_sync(0xffffffffu, mxl);
        int wct = __reduce_add_sync(0xffffffffu, cnt);
        if (lane == c - 1) {
            mypk = (wct == 0) ? 0u
                 : ((unsigned)wmn | ((unsigned)wmx << 10) | ((unsigned)wct << 20));
        }
    }
    return mypk;
}

__global__ __launch_bounds__(160) void k_rowstats(const float* __restrict__ logits) {
    const int rowA = blockIdx.x * 2;
    const int b    = blockIdx.y;
    const int t    = threadIdx.x;
    const int lane = t & 31;
    const int warp = t >> 5;
    const int col0 = t << 2;   // 4 pixels per thread

    // All 14 independent loads issued before any use (MLP=14).
    float4 va[NCLS], vb[NCLS];
#pragma unroll
    for (int c = 0; c < NCLS; c++) {
        const float* p = logits + (((size_t)b * NCLS + c) * HH + rowA) * WW + col0;
        va[c] = *reinterpret_cast<const float4*>(p);
        vb[c] = *reinterpret_cast<const float4*>(p + WW);
    }

    unsigned pkA = seg_stats(va, col0, lane);
    unsigned pkB = seg_stats(vb, col0, lane);

    if (lane < 6) {
        const int base = ((b * 6 + lane) * HH + rowA) * 8 + warp;
        g_row5[base]     = pkA;
        g_row5[base + 8] = pkB;
    }
}

// -------------------------------------------------------------------------
// Kernel 2: one 32-thread block per segment (96 blocks). Lane owns 12
// contiguous rows; all 24 uint4 loads issued fully unrolled up-front
// (MLP=24), then fold 5 warp-slots per row, ordered in-lane merge, 5-step
// ordered warp tree. No smem, no barriers.
// -------------------------------------------------------------------------
__global__ __launch_bounds__(32) void k_combine() {
    const int seg  = blockIdx.x;
    const int lane = threadIdx.x;
    const int r0   = lane * 12;   // rows [r0, r0+12); 12*32=384 covers HH=368

    uint4 ua[12], ub[12];
#pragma unroll
    for (int i = 0; i < 12; i++) {
        const int r = r0 + i;
        if (r < HH) {
            const uint4* p = reinterpret_cast<const uint4*>(&g_row5[(seg * HH + r) * 8]);
            ua[i] = p[0];
            ub[i] = p[1];
        } else {
            ua[i] = make_uint4(0, 0, 0, 0);
            ub[i] = make_uint4(0, 0, 0, 0);
        }
    }

    int valid = 0, cnt = 0, S = 0;
    int fcol = 0, frow = 0, lcol = 0, lrow = 0;

#pragma unroll
    for (int i = 0; i < 12; i++) {
        const int r = r0 + i;
        unsigned pks[5] = {ua[i].x, ua[i].y, ua[i].z, ua[i].w, ub[i].x};
        int rc = 0, mnv = 0x7fffffff, mxv = -1;
#pragma unroll
        for (int s = 0; s < 5; s++) {
            unsigned pk = pks[s];
            int c = pk >> 20;
            if (c) {
                rc += c;
                mnv = min(mnv, (int)(pk & 1023));
                mxv = max(mxv, (int)((pk >> 10) & 1023));
            }
        }
        if (rc) {
            if (valid) {
                S += abs((mnv - r) - (lcol - lrow));
            } else {
                fcol = mnv; frow = r; valid = 1;
            }
            S += mxv - mnv;
            lcol = mxv; lrow = r; cnt += rc;
        }
    }

    // Ordered warp tree: lane absorbs the segment from lane+off (its right).
#pragma unroll
    for (int off = 1; off < 32; off <<= 1) {
        int ov  = __shfl_down_sync(0xffffffffu, valid, off);
        int oc  = __shfl_down_sync(0xffffffffu, cnt, off);
        int oS  = __shfl_down_sync(0xffffffffu, S, off);
        int ofc = __shfl_down_sync(0xffffffffu, fcol, off);
        int ofr = __shfl_down_sync(0xffffffffu, frow, off);
        int olc = __shfl_down_sync(0xffffffffu, lcol, off);
        int olr = __shfl_down_sync(0xffffffffu, lrow, off);
        if ((lane & (2 * off - 1)) == 0 && ov) {
            if (valid) {
                S += oS + abs((ofc - ofr) - (lcol - lrow));
            } else {
                S = oS; fcol = ofc; frow = ofr; valid = 1;
            }
            cnt += oc;
            lcol = olc; lrow = olr;
        }
    }

    if (lane == 0) {
        float loss = 0.0f;
        if (cnt >= 2) {
            loss = ((float)S / (float)(cnt - 1)) / (float)(cnt + 1);
        }
        g_part[seg] = loss;
    }
}

// -------------------------------------------------------------------------
// Kernel 3: deterministic sum of the 96 partials -> d_out[0].
// -------------------------------------------------------------------------
__global__ __launch_bounds__(128) void k_final(float* __restrict__ out) {
    const int t = threadIdx.x;
    float v = (t < NSEG) ? g_part[t] : 0.0f;
#pragma unroll
    for (int off = 16; off > 0; off >>= 1)
        v += __shfl_down_sync(0xffffffffu, v, off);
    __shared__ float sh[4];
    if ((t & 31) == 0) sh[t >> 5] = v;
    __syncthreads();
    if (t == 0) out[0] = (sh[0] + sh[1]) + (sh[2] + sh[3]);
}

extern "C" void kernel_launch(void* const* d_in, const int* in_sizes, int n_in,
                              void* d_out, int out_size) {
    const float* logits = (const float*)d_in[0];
    // d_in[1] (labels) is unused by the reference computation.
    dim3 g1(HH / 2, BATCH);
    k_rowstats<<<g1, 160>>>(logits);
    k_combine<<<NSEG, 32>>>();
    k_final<<<1, 128>>>((float*)d_out);
}

// round 12
// speedup vs baseline: 1.1014x; 1.0889x over previous
#include <cuda_runtime.h>
#include <cstdint>

#define BATCH 16
#define NCLS 7
#define HH 368
#define WW 640
#define NSEG (BATCH * 6)

// Per-(b, class, row, warp) packed stats, padded to 8 words/row (32B) for
// aligned uint4 reads. Word: bits[0:10)=min col, [10:20)=max col,
// [20:31)=count (0 means empty for this class in this warp's 128 cols).
// Only warp-slots 0..4 are written; slots 5..7 stay zero (never written).
__device__ unsigned g_row5[NSEG * HH * 8];
__device__ float g_part[NSEG];
__device__ int g_done = 0;

__device__ __forceinline__ int atom_add_acqrel1(int* p) {
    int old;
    asm volatile("atom.acq_rel.gpu.global.add.s32 %0, [%1], 1;"
                 : "=r"(old) : "l"(p) : "memory");
    return old;
}

// -------------------------------------------------------------------------
// Kernel 1 (unchanged, plateaued at ~21.3us): per-pixel class via
// soft-argmax -> per-WARP per-class (min,max,count) stored directly.
// One 160-thread block covers TWO rows; 14 independent float4 loads/thread.
// -------------------------------------------------------------------------
__device__ __forceinline__ int pix_class(const float l[7]) {
    float e0 = __expf(l[0]);
    float e1 = __expf(l[1]);
    float e2 = __expf(l[2]);
    float e3 = __expf(l[3]);
    float e4 = __expf(l[4]);
    float e5 = __expf(l[5]);
    float e6 = __expf(l[6]);
    float den = ((e0 + e1) + (e2 + e3)) + ((e4 + e5) + e6);
    float num = e1;
    num = fmaf(2.0f, e2, num);
    num = fmaf(3.0f, e3, num);
    num = fmaf(4.0f, e4, num);
    num = fmaf(5.0f, e5, num);
    num = fmaf(6.0f, e6, num);
    // num/den in [0,6]; truncation == floor for non-negative values.
    float r = __fdividef(num, den);
    return (int)r;
}

__device__ __forceinline__ unsigned seg_stats(const float4 v[NCLS], int col0, int lane) {
    int k0, k1, k2, k3;
    {
        float l[7];
#pragma unroll
        for (int c = 0; c < NCLS; c++) l[c] = v[c].x;
        k0 = pix_class(l);
#pragma unroll
        for (int c = 0; c < NCLS; c++) l[c] = v[c].y;
        k1 = pix_class(l);
#pragma unroll
        for (int c = 0; c < NCLS; c++) l[c] = v[c].z;
        k2 = pix_class(l);
#pragma unroll
        for (int c = 0; c < NCLS; c++) l[c] = v[c].w;
        k3 = pix_class(l);
    }

    // One-hot bitboard: byte j holds (1 << class_of_pixel_j).
    const unsigned B = (1u << k0) | (1u << (k1 + 8)) | (1u << (k2 + 16)) | (1u << (k3 + 24));

    unsigned mypk = 0;  // lane c-1 keeps class c's packed stats

#pragma unroll
    for (int c = 1; c <= 6; c++) {
        unsigned m = (B >> c) & 0x01010101u;  // bit 8*j set iff pixel j is class c
        int cnt = __popc(m);
        int mnl = m ? col0 + ((__ffs(m) - 1) >> 3) : 0x7fffffff;
        int mxl = m ? col0 + ((31 - __clz(m)) >> 3) : -1;
        int wmn = __reduce_min_sync(0xffffffffu, mnl);
        int wmx = __reduce_max_sync(0xffffffffu, mxl);
        int wct = __reduce_add_sync(0xffffffffu, cnt);
        if (lane == c - 1) {
            mypk = (wct == 0) ? 0u
                 : ((unsigned)wmn | ((unsigned)wmx << 10) | ((unsigned)wct << 20));
        }
    }
    return mypk;
}

__global__ __launch_bounds__(160) void k_rowstats(const float* __restrict__ logits) {
    const int rowA = blockIdx.x * 2;
    const int b    = blockIdx.y;
    const int t    = threadIdx.x;
    const int lane = t & 31;
    const int warp = t >> 5;
    const int col0 = t << 2;   // 4 pixels per thread

    // All 14 independent loads issued before any use (MLP=14).
    float4 va[NCLS], vb[NCLS];
#pragma unroll
    for (int c = 0; c < NCLS; c++) {
        const float* p = logits + (((size_t)b * NCLS + c) * HH + rowA) * WW + col0;
        va[c] = *reinterpret_cast<const float4*>(p);
        vb[c] = *reinterpret_cast<const float4*>(p + WW);
    }

    unsigned pkA = seg_stats(va, col0, lane);
    unsigned pkB = seg_stats(vb, col0, lane);

    if (lane < 6) {
        const int base = ((b * 6 + lane) * HH + rowA) * 8 + warp;
        g_row5[base]     = pkA;
        g_row5[base + 8] = pkB;
    }
}

// -------------------------------------------------------------------------
// Kernel 2 (combine + finish): one 32-thread block per segment (96 blocks).
// Lane owns 12 contiguous rows; all 24 uint4 loads issued unrolled up-front
// (MLP=24), fold 5 warp-slots per row, ordered in-lane merge, 5-step
// ordered warp tree. Lane 0 publishes g_part[seg] and elects a finisher via
// one acq_rel atomic (release orders the store; the finisher's acquire in
// the RMW chain makes all 96 partials visible). The electing block's warp
// sums the partials in fixed index order (deterministic) -> out[0].
// -------------------------------------------------------------------------
__global__ __launch_bounds__(32) void k_combine(float* __restrict__ out) {
    const int seg  = blockIdx.x;
    const int lane = threadIdx.x;
    const int r0   = lane * 12;   // rows [r0, r0+12); 12*32=384 covers HH=368

    uint4 ua[12], ub[12];
#pragma unroll
    for (int i = 0; i < 12; i++) {
        const int r = r0 + i;
        if (r < HH) {
            const uint4* p = reinterpret_cast<const uint4*>(&g_row5[(seg * HH + r) * 8]);
            ua[i] = p[0];
            ub[i] = p[1];
        } else {
            ua[i] = make_uint4(0, 0, 0, 0);
            ub[i] = make_uint4(0, 0, 0, 0);
        }
    }

    int valid = 0, cnt = 0, S = 0;
    int fcol = 0, frow = 0, lcol = 0, lrow = 0;

#pragma unroll
    for (int i = 0; i < 12; i++) {
        const int r = r0 + i;
        unsigned pks[5] = {ua[i].x, ua[i].y, ua[i].z, ua[i].w, ub[i].x};
        int rc = 0, mnv = 0x7fffffff, mxv = -1;
#pragma unroll
        for (int s = 0; s < 5; s++) {
            unsigned pk = pks[s];
            int c = pk >> 20;
            if (c) {
                rc += c;
                mnv = min(mnv, (int)(pk & 1023));
                mxv = max(mxv, (int)((pk >> 10) & 1023));
            }
        }
        if (rc) {
            if (valid) {
                S += abs((mnv - r) - (lcol - lrow));
            } else {
                fcol = mnv; frow = r; valid = 1;
            }
            S += mxv - mnv;
            lcol = mxv; lrow = r; cnt += rc;
        }
    }

    // Ordered warp tree: lane absorbs the segment from lane+off (its right).
#pragma unroll
    for (int off = 1; off < 32; off <<= 1) {
        int ov  = __shfl_down_sync(0xffffffffu, valid, off);
        int oc  = __shfl_down_sync(0xffffffffu, cnt, off);
        int oS  = __shfl_down_sync(0xffffffffu, S, off);
        int ofc = __shfl_down_sync(0xffffffffu, fcol, off);
        int ofr = __shfl_down_sync(0xffffffffu, frow, off);
        int olc = __shfl_down_sync(0xffffffffu, lcol, off);
        int olr = __shfl_down_sync(0xffffffffu, lrow, off);
        if ((lane & (2 * off - 1)) == 0 && ov) {
            if (valid) {
                S += oS + abs((ofc - ofr) - (lcol - lrow));
            } else {
                S = oS; fcol = ofc; frow = ofr; valid = 1;
            }
            cnt += oc;
            lcol = olc; lrow = olr;
        }
    }

    int is_last = 0;
    if (lane == 0) {
        float loss = 0.0f;
        if (cnt >= 2) {
            loss = ((float)S / (float)(cnt - 1)) / (float)(cnt + 1);
        }
        g_part[seg] = loss;
        // Publish + elect finisher (release orders the store above).
        is_last = (atom_add_acqrel1(&g_done) == NSEG - 1);
    }
    is_last = __shfl_sync(0xffffffffu, is_last, 0);

    if (is_last) {
        // Fixed-order deterministic reduction of the 96 partials.
        float v = __ldcg(&g_part[lane]) + __ldcg(&g_part[lane + 32])
                + __ldcg(&g_part[lane + 64]);
#pragma unroll
        for (int off = 16; off > 0; off >>= 1)
            v += __shfl_down_sync(0xffffffffu, v, off);
        if (lane == 0) {
            out[0] = v;
            g_done = 0;  // reset for next graph replay
        }
    }
}

extern "C" void kernel_launch(void* const* d_in, const int* in_sizes, int n_in,
                              void* d_out, int out_size) {
    const float* logits = (const float*)d_in[0];
    // d_in[1] (labels) is unused by the reference computation.
    dim3 g1(HH / 2, BATCH);
    k_rowstats<<<g1, 160>>>(logits);
    k_combine<<<NSEG, 32>>>((float*)d_out);
}